// round 11
// baseline (speedup 1.0000x reference)
#include <cuda_runtime.h>
#include <cuda_fp16.h>
#include <cstdint>

// relu(X[131072,256] @ W[256,256]^T + b), fp32.
// R10: fp16 HGEMM, whole W (128KB) + whole X tile (64KB) resident in smem.
// ONE barrier per CTA; 16-step MMA mainloop with cross-kk fragment pipelining,
// no cp.async / converts / barriers inside the loop.

#define KDIM 256
#define NDIM 256
#define BM   128
#define NTHR 512

#define SM_BIAS  0
#define SM_XT    1024                  // 4 chunks of 128 rows x 128B = 64KB
#define SM_W     (1024 + 65536)       // 4 chunks of 256 rows x 128B = 128KB
#define SMEM_TOTAL (SM_W + 131072)    // 197632

__device__ __forceinline__ uint32_t smem_u32(const void* p) {
    uint32_t a;
    asm("{ .reg .u64 t; cvta.to.shared.u64 t, %1; cvt.u32.u64 %0, t; }" : "=r"(a) : "l"(p));
    return a;
}

__device__ __forceinline__ void cp_async16(uint32_t dst, const void* src) {
    asm volatile("cp.async.cg.shared.global [%0], [%1], 16;" :: "r"(dst), "l"(src) : "memory");
}
__device__ __forceinline__ void cp_commit() {
    asm volatile("cp.async.commit_group;" ::: "memory");
}
__device__ __forceinline__ void cp_wait0() {
    asm volatile("cp.async.wait_group 0;" ::: "memory");
}

__device__ __forceinline__ void ldm_x4(uint32_t addr, uint32_t* r) {
    asm volatile("ldmatrix.sync.aligned.m8n8.x4.shared.b16 {%0,%1,%2,%3}, [%4];"
                 : "=r"(r[0]), "=r"(r[1]), "=r"(r[2]), "=r"(r[3]) : "r"(addr));
}

__device__ __forceinline__ void mma16816(float* c, const uint32_t* a, uint32_t b0, uint32_t b1) {
    asm volatile(
        "mma.sync.aligned.m16n8k16.row.col.f32.f16.f16.f32 "
        "{%0,%1,%2,%3}, {%4,%5,%6,%7}, {%8,%9}, {%0,%1,%2,%3};"
        : "+f"(c[0]), "+f"(c[1]), "+f"(c[2]), "+f"(c[3])
        : "r"(a[0]), "r"(a[1]), "r"(a[2]), "r"(a[3]), "r"(b0), "r"(b1));
}

__device__ __half g_Wh[NDIM * KDIM];

__global__ void split_w_kernel(const float* __restrict__ W) {
    int i = blockIdx.x * 256 + threadIdx.x;
    g_Wh[i] = __float2half_rn(W[i]);
}

// convert one float4 (4 K values) -> fp16, store swizzled into a 128B-row tile
__device__ __forceinline__ void conv_store(float4 v, char* tile, int row, int c) {
    __half h0 = __float2half_rn(v.x);
    __half h1 = __float2half_rn(v.y);
    __half h2 = __float2half_rn(v.z);
    __half h3 = __float2half_rn(v.w);
    uint2 hv;
    hv.x = (uint32_t)__half_as_ushort(h0) | ((uint32_t)__half_as_ushort(h1) << 16);
    hv.y = (uint32_t)__half_as_ushort(h2) | ((uint32_t)__half_as_ushort(h3) << 16);
    uint32_t off = (uint32_t)(row * 128 + c * 8);
    uint32_t swo = off ^ ((off >> 3) & 0x70);
    *(uint2*)(tile + swo) = hv;
}

__global__ __launch_bounds__(NTHR, 1)
void gemm_hmma_kernel(const float* __restrict__ X,
                      const float* __restrict__ bias,
                      float* __restrict__ out) {
    extern __shared__ char sm[];
    const uint32_t smb = smem_u32(sm);
    const int tid  = threadIdx.x;
    const int wid  = tid >> 5;
    const int lane = tid & 31;
    const int bx   = blockIdx.x;

    const int wm = wid & 3;        // M quarter (32 rows)
    const int wn = wid >> 2;       // N quarter (64 cols)

    if (tid < 256) ((float*)(sm + SM_BIAS))[tid] = bias[tid];

    const float* Xblk = X + (size_t)bx * BM * KDIM;

    const uint32_t swx     = (uint32_t)(lane & 7) << 4;
    const int a_mrow       = wm * 32 + (lane & 7) + ((lane >> 3) & 1) * 8;
    const uint32_t a_khalf = (uint32_t)(lane >> 4) * 16;
    const int b_nrow       = wn * 64 + (lane & 7) + ((lane >> 4) ? 8 : 0);
    const uint32_t b_khalf = (uint32_t)((lane >> 3) & 1) * 16;

    float acc[2][8][4];
    #pragma unroll
    for (int i = 0; i < 2; i++)
        #pragma unroll
        for (int j = 0; j < 8; j++)
            #pragma unroll
            for (int q = 0; q < 4; q++) acc[i][j][q] = 0.0f;

    // ================= prologue: load ALL of W and X tile =================
    // W: 8192 x 16B copies, 16 per thread, into 4 chunks of [256 x 128B]
    #pragma unroll
    for (int it = 0; it < 16; it++) {
        int id = tid + it * NTHR;          // 0..8191
        int r  = id >> 5;                  // W row 0..255
        int ks = id & 31;                  // 16B slot (8 fp16) within row
        int kch = ks >> 3, c = ks & 7;
        uint32_t off = (uint32_t)(r * 128 + c * 16);
        uint32_t swo = off ^ ((off >> 3) & 0x70);
        cp_async16(smb + SM_W + (uint32_t)(kch * 32768) + swo, g_Wh + r * KDIM + ks * 8);
    }
    cp_commit();

    // X: 8192 float4, 16 per thread -> convert -> 4 chunks of [128 x 128B]
    {
        float4 xv[16];
        #pragma unroll
        for (int it = 0; it < 16; it++) {
            int id = tid + it * NTHR;      // 0..8191
            int row = id >> 6;             // 0..127
            int slot = id & 63;            // float4 slot within row
            xv[it] = *(const float4*)(Xblk + (size_t)row * KDIM + slot * 4);
        }
        #pragma unroll
        for (int it = 0; it < 16; it++) {
            int id = tid + it * NTHR;
            int row = id >> 6;
            int slot = id & 63;
            int kch = slot >> 4, c = slot & 15;
            conv_store(xv[it], sm + SM_XT + kch * 16384, row, c);
        }
    }
    cp_wait0();
    __syncthreads();                       // the ONLY block barrier

    // ================= mainloop: 16 kk, barrier-free, frag-pipelined =======
    const uint32_t aRow = smb + SM_XT + (uint32_t)(a_mrow * 128);
    const uint32_t bRow = smb + SM_W  + (uint32_t)(b_nrow * 128);

    // addr helpers (constants after unroll)
    #define A_ADDR(kk)     (aRow + (uint32_t)(((kk) >> 2) * 16384) + ((((uint32_t)(kk) & 3) * 32 + a_khalf) ^ swx))
    #define B_ADDR(kk, ng) (bRow + (uint32_t)(((kk) >> 2) * 32768) + (uint32_t)((ng) * 2048) + ((((uint32_t)(kk) & 3) * 32 + b_khalf) ^ swx))

    uint32_t ah[2][2][4];   // [kk buf][mb][frag]
    uint32_t bh[2][4];      // ng stream double buffer

    ldm_x4(A_ADDR(0),        ah[0][0]);
    ldm_x4(A_ADDR(0) + 2048, ah[0][1]);
    ldm_x4(B_ADDR(0, 0),     bh[0]);

    #pragma unroll
    for (int kk = 0; kk < 16; kk++) {
        const int kb = kk & 1;
        #pragma unroll
        for (int ng = 0; ng < 4; ng++) {
            const int cb = ng & 1;
            if (ng < 3) {
                ldm_x4(B_ADDR(kk, ng + 1), bh[cb ^ 1]);
            } else if (kk < 15) {
                ldm_x4(B_ADDR(kk + 1, 0), bh[0]);        // bh[0] free after ng=2
            }
            if (ng == 1 && kk < 15) {
                ldm_x4(A_ADDR(kk + 1),        ah[kb ^ 1][0]);
                ldm_x4(A_ADDR(kk + 1) + 2048, ah[kb ^ 1][1]);
            }
            mma16816(acc[0][2 * ng + 0], ah[kb][0], bh[cb][0], bh[cb][1]);
            mma16816(acc[0][2 * ng + 1], ah[kb][0], bh[cb][2], bh[cb][3]);
            mma16816(acc[1][2 * ng + 0], ah[kb][1], bh[cb][0], bh[cb][1]);
            mma16816(acc[1][2 * ng + 1], ah[kb][1], bh[cb][2], bh[cb][3]);
        }
    }
    #undef A_ADDR
    #undef B_ADDR

    // ================= epilogue: bias + relu =================
    const float* sb = (const float*)(sm + SM_BIAS);
    const int mbase = bx * BM + wm * 32 + (lane >> 2);
    const int nbase = wn * 64 + (lane & 3) * 2;

    #pragma unroll
    for (int mb = 0; mb < 2; mb++) {
        #pragma unroll
        for (int nb = 0; nb < 8; nb++) {
            const int n = nbase + nb * 8;
            const float b0 = sb[n], b1 = sb[n + 1];
            const int m0 = mbase + mb * 16;
            float2 v0, v1;
            v0.x = fmaxf(acc[mb][nb][0] + b0, 0.0f);
            v0.y = fmaxf(acc[mb][nb][1] + b1, 0.0f);
            v1.x = fmaxf(acc[mb][nb][2] + b0, 0.0f);
            v1.y = fmaxf(acc[mb][nb][3] + b1, 0.0f);
            *(float2*)(out + (size_t)m0 * NDIM + n) = v0;
            *(float2*)(out + (size_t)(m0 + 8) * NDIM + n) = v1;
        }
    }
}

extern "C" void kernel_launch(void* const* d_in, const int* in_sizes, int n_in,
                              void* d_out, int out_size) {
    const float* X    = (const float*)d_in[0];
    const float* W    = (const float*)d_in[1];
    const float* bias = (const float*)d_in[2];
    float* out = (float*)d_out;

    cudaFuncSetAttribute(gemm_hmma_kernel,
                         cudaFuncAttributeMaxDynamicSharedMemorySize, SMEM_TOTAL);

    split_w_kernel<<<(NDIM * KDIM) / 256, 256>>>(W);

    const int Brows = in_sizes[0] / KDIM;
    gemm_hmma_kernel<<<Brows / BM, NTHR, SMEM_TOTAL>>>(X, bias, out);
}